// round 10
// baseline (speedup 1.0000x reference)
#include <cuda_runtime.h>
#include <math.h>

#define Nn 2000
#define Ee 20000
#define Cc 16
#define Bb 128
#define EPS 1e-5f
#define CHUNK 128

typedef unsigned long long u64;

__device__ __forceinline__ bool is_func(int n) { return n >= 200 && n < 1800; }

// ---- packed f32x2 helpers ---------------------------------------------------
__device__ __forceinline__ u64 fma2(u64 a, u64 b, u64 c) {
    u64 d;
    asm("fma.rn.f32x2 %0, %1, %2, %3;" : "=l"(d) : "l"(a), "l"(b), "l"(c));
    return d;
}
__device__ __forceinline__ u64 splat2(float x) {
    u64 d;
    unsigned r = __float_as_uint(x);
    asm("mov.b64 %0, {%1, %1};" : "=l"(d) : "r"(r));
    return d;
}
__device__ __forceinline__ void unpack2(u64 v, float& lo, float& hi) {
    unsigned a, b;
    asm("mov.b64 {%0, %1}, %2;" : "=r"(a), "=r"(b) : "l"(v));
    lo = __uint_as_float(a); hi = __uint_as_float(b);
}
__device__ __forceinline__ u64 pack2(float lo, float hi) {
    u64 d;
    unsigned a = __float_as_uint(lo), b = __float_as_uint(hi);
    asm("mov.b64 %0, {%1, %2};" : "=l"(d) : "r"(a), "r"(b));
    return d;
}

// ---------------- device scratch (allocation-free) --------------------------
__device__ float g_xT[Nn * Bb];
__device__ float g_xeA[Ee * Bb];
__device__ float g_xeB[Ee * Bb];
__device__ float g_pw1[Ee * Cc];
__device__ float g_pw3m[Ee * Cc];
__device__ float g_pb3[Ee];
__device__ int   g_psrcd[Ee];
__device__ int   g_rowidx[Ee];
__device__ float g_osum[200 * Bb];     // compact output-node sums
__device__ int   g_cntD[Nn], g_cntS[Nn];   // zero at load; re-zeroed by k_out
__device__ int   g_rsD[Nn + 1], g_rsS[Nn + 1];
__device__ int   g_curD[Nn], g_curS[Nn];

// ---------------- preprocessing ---------------------------------------------
// Tiled transpose of x (B=128 x N=2000) -> xT (N x B); histogram rides along.
__global__ void __launch_bounds__(256) k_init(
        const float* __restrict__ x,
        const int* __restrict__ src, const int* __restrict__ dst) {
    __shared__ float tile[32][33];
    // grid: (63, 4). Each block: 32x32 tile, threads 32x8.
    int bx = blockIdx.x, by = blockIdx.y;
    int tx = threadIdx.x & 31, ty = threadIdx.x >> 5;   // 32 x 8
    int n0 = bx * 32, b0 = by * 32;
#pragma unroll
    for (int k = 0; k < 32; k += 8) {
        int n = n0 + tx, b = b0 + ty + k;
        if (n < Nn) tile[ty + k][tx] = x[b * Nn + n];
    }
    __syncthreads();
#pragma unroll
    for (int k = 0; k < 32; k += 8) {
        int n = n0 + ty + k, b = b0 + tx;
        if (n < Nn) g_xT[n * Bb + b] = tile[tx][ty + k];
    }
    // histogram (linear ids across the whole grid cover Ee)
    int t = (blockIdx.y * gridDim.x + blockIdx.x) * 256 + threadIdx.x;
    if (t < Ee) {
        atomicAdd(&g_cntD[dst[t]], 1);
        atomicAdd(&g_cntS[src[t]], 1);
    }
}

__global__ void __launch_bounds__(1024) k_scan() {
    __shared__ int sh[2048];
    const int* cnt = blockIdx.x ? g_cntS : g_cntD;
    int* rs  = blockIdx.x ? g_rsS : g_rsD;
    int* cur = blockIdx.x ? g_curS : g_curD;
    int t = threadIdx.x;
    sh[t]        = (t < Nn) ? cnt[t] : 0;
    sh[t + 1024] = (t + 1024 < Nn) ? cnt[t + 1024] : 0;
    __syncthreads();
    for (int off = 1; off < 2048; off <<= 1) {
        int v0 = (t >= off) ? sh[t - off] : 0;
        int v1 = (t + 1024 >= off) ? sh[t + 1024 - off] : 0;
        __syncthreads();
        sh[t] += v0;
        sh[t + 1024] += v1;
        __syncthreads();
    }
    if (t < Nn) {
        int v = (t == 0) ? 0 : sh[t - 1];
        rs[t] = v; cur[t] = v;
    }
    int i2 = t + 1024;
    if (i2 < Nn) {
        int v = sh[i2 - 1];
        rs[i2] = v; cur[i2] = v;
    }
    if (t == 0) rs[Nn] = sh[Nn - 1];
}

__global__ void __launch_bounds__(256) k_build(
        const float* __restrict__ w1, const float* __restrict__ w3,
        const float* __restrict__ b3,
        const int* __restrict__ src, const int* __restrict__ dst) {
    __shared__ int sE[256], sPd[256], sPs[256];
    __shared__ float sFm[256];
    int e = blockIdx.x * 256 + threadIdx.x;
    int nEdge = min(256, Ee - blockIdx.x * 256);
    if (e < Ee) {
        int s = src[e], d = dst[e];
        int pd = atomicAdd(&g_curD[d], 1);
        int ps = atomicAdd(&g_curS[s], 1);
        g_psrcd[pd]  = s * Bb;
        g_rowidx[pd] = ps * Bb;
        g_pb3[ps]    = b3[e];
        sE[threadIdx.x]  = e;
        sPd[threadIdx.x] = pd;
        sPs[threadIdx.x] = ps;
        sFm[threadIdx.x] = is_func(s) ? 1.0f : 0.0f;
    }
    __syncthreads();
    for (int i = threadIdx.x; i < nEdge * 16; i += 256) {
        int j = i >> 4, c = i & 15;
        int e2 = sE[j];
        g_pw1[sPd[j] * 16 + c]  = w1[e2 * 16 + c];
        g_pw3m[sPs[j] * 16 + c] = w3[e2 * 16 + c] * sFm[j];
    }
}

// ---------------- shared layout ----------------------------------------------
struct SmemT {
    union {
        float4 stage4[CHUNK * 4];
        float  stage[CHUNK * 16];
        float  shh[128][17];
    };
    float4 shw4[16][4];
    float  shs[8][16], shs2[8][16];
    float  shscale[16], shshift[16];
    int    sidx[CHUNK];
    float  sb3[CHUNK];
};

// ---------------- BN + ELU ---------------------------------------------------
__device__ __forceinline__ void bn_elu(float* acc, int n, int b,
                                       const float* __restrict__ gamma,
                                       const float* __restrict__ beta,
                                       SmemT* sm) {
    __syncthreads();
#pragma unroll
    for (int c = 0; c < 16; c++) sm->shh[b][c] = acc[c];
    __syncthreads();
    int c0 = b & 15, gg = b >> 4;
    float s = 0.f, s2 = 0.f;
#pragma unroll
    for (int k = 0; k < 16; k++) {
        float v = sm->shh[gg + 8 * k][c0];
        s += v; s2 += v * v;
    }
    sm->shs[gg][c0] = s;
    sm->shs2[gg][c0] = s2;
    __syncthreads();
    if (b < 16) {
        float S = 0.f, S2 = 0.f;
#pragma unroll
        for (int g = 0; g < 8; g++) { S += sm->shs[g][b]; S2 += sm->shs2[g][b]; }
        float m   = S * (1.0f / 128.0f);
        float var = S2 * (1.0f / 128.0f) - m * m;
        float rsg = rsqrtf(var + EPS);
        float sc  = gamma[n * 16 + b] * rsg;
        sm->shscale[b] = sc;
        sm->shshift[b] = beta[n * 16 + b] - m * sc;
    }
    __syncthreads();
#pragma unroll
    for (int c = 0; c < 16; c++) {
        float v = acc[c] * sm->shscale[c] + sm->shshift[c];
        acc[c] = v > 0.f ? v : (__expf(v) - 1.0f);
    }
}

// ---------------- fused per-layer kernel -------------------------------------
__global__ void __launch_bounds__(128, 12) k_layer(
    const float* __restrict__ xe_rows, int use_psrc,
    float* __restrict__ xe_out,
    const float* __restrict__ b1, const float* __restrict__ w2,
    const float* __restrict__ b2,
    const float* __restrict__ g1, const float* __restrict__ be1,
    const float* __restrict__ g2, const float* __restrict__ be2) {
    __shared__ SmemT sm;
    int t = blockIdx.x;
    int b = threadIdx.x;

    if (t >= 1600) {   // const-edge writer (layer-0 grid only)
        int i = t - 1600;
        int n = (i < 200) ? i : (1600 + i);
        float xb = g_xT[n * Bb + b];
        int qs = g_rsS[n], qe = g_rsS[n + 1];
        for (int q = qs; q < qe; q++) {
            float v = xb + g_pb3[q];
            g_xeA[q * Bb + b] = v;
            g_xeB[q * Bb + b] = v;
        }
        return;
    }

    int n = 200 + t;
    const int* rowix = use_psrc ? g_psrcd : g_rowidx;

    u64 acc2[8];
    {
        const ulonglong2* bp = (const ulonglong2*)(b1 + n * 16);
#pragma unroll
        for (int k = 0; k < 4; k++) {
            ulonglong2 q = bp[k];
            acc2[2 * k] = q.x; acc2[2 * k + 1] = q.y;
        }
    }

    // ---- gather ----
    int rs = g_rsD[n], re = g_rsD[n + 1];
    for (int cbase = rs; cbase < re; cbase += CHUNK) {
        int cnt = min(CHUNK, re - cbase);
        __syncthreads();
        for (int i = b; i < cnt * 16; i += 128) sm.stage[i] = g_pw1[cbase * 16 + i];
        if (b < cnt) sm.sidx[b] = rowix[cbase + b];
        __syncthreads();
        for (int jb = 0; jb < cnt; jb += 8) {
            float xv[8];
#pragma unroll
            for (int j = 0; j < 8; j++) {
                int jj = jb + j;
                xv[j] = (jj < cnt) ? xe_rows[sm.sidx[jj] + b] : 0.0f;
            }
#pragma unroll
            for (int j = 0; j < 8; j++) {
                int jj = jb + j;
                if (jj < cnt) {
                    u64 xv2 = splat2(xv[j]);
                    const ulonglong2* wp = (const ulonglong2*)&sm.stage[jj * 16];
                    ulonglong2 q0 = wp[0], q1 = wp[1], q2 = wp[2], q3 = wp[3];
                    acc2[0] = fma2(q0.x, xv2, acc2[0]);
                    acc2[1] = fma2(q0.y, xv2, acc2[1]);
                    acc2[2] = fma2(q1.x, xv2, acc2[2]);
                    acc2[3] = fma2(q1.y, xv2, acc2[3]);
                    acc2[4] = fma2(q2.x, xv2, acc2[4]);
                    acc2[5] = fma2(q2.y, xv2, acc2[5]);
                    acc2[6] = fma2(q3.x, xv2, acc2[6]);
                    acc2[7] = fma2(q3.y, xv2, acc2[7]);
                }
            }
        }
    }

    float acc[16];
#pragma unroll
    for (int k = 0; k < 8; k++) unpack2(acc2[k], acc[2 * k], acc[2 * k + 1]);

    bn_elu(acc, n, b, g1, be1, &sm);

    // ---- 16x16 matmul ----
    __syncthreads();
#pragma unroll
    for (int c = 0; c < 16; c++) sm.shh[b][c] = acc[c];
    {
        const float4* w2p = (const float4*)(w2 + n * 256);
        for (int i = b; i < 64; i += 128) sm.shw4[i >> 2][i & 3] = w2p[i];
    }
    __syncthreads();

    u64 out2[8];
    {
        const ulonglong2* bp = (const ulonglong2*)(b2 + n * 16);
#pragma unroll
        for (int k = 0; k < 4; k++) {
            ulonglong2 q = bp[k];
            out2[2 * k] = q.x; out2[2 * k + 1] = q.y;
        }
    }
#pragma unroll
    for (int c = 0; c < 16; c++) {
        u64 v2 = splat2(sm.shh[b][c]);
        const ulonglong2* wp = (const ulonglong2*)&sm.shw4[c][0];
        ulonglong2 q0 = wp[0], q1 = wp[1], q2 = wp[2], q3 = wp[3];
        out2[0] = fma2(q0.x, v2, out2[0]);
        out2[1] = fma2(q0.y, v2, out2[1]);
        out2[2] = fma2(q1.x, v2, out2[2]);
        out2[3] = fma2(q1.y, v2, out2[3]);
        out2[4] = fma2(q2.x, v2, out2[4]);
        out2[5] = fma2(q2.y, v2, out2[5]);
        out2[6] = fma2(q3.x, v2, out2[6]);
        out2[7] = fma2(q3.y, v2, out2[7]);
    }

    float out[16];
#pragma unroll
    for (int k = 0; k < 8; k++) unpack2(out2[k], out[2 * k], out[2 * k + 1]);

    bn_elu(out, n, b, g2, be2, &sm);

#pragma unroll
    for (int k = 0; k < 8; k++) out2[k] = pack2(out[2 * k], out[2 * k + 1]);

    // ---- scatter ----
    float xb = g_xT[n * Bb + b];
    int qs = g_rsS[n], qe = g_rsS[n + 1];
    for (int cbase = qs; cbase < qe; cbase += CHUNK) {
        int cnt = min(CHUNK, qe - cbase);
        __syncthreads();
        for (int i = b; i < cnt * 16; i += 128) sm.stage[i] = g_pw3m[cbase * 16 + i];
        if (b < cnt) sm.sb3[b] = g_pb3[cbase + b];
        __syncthreads();
        for (int j = 0; j < cnt; j++) {
            const ulonglong2* wq = (const ulonglong2*)&sm.stage[j * 16];
            ulonglong2 q0 = wq[0], q1 = wq[1], q2 = wq[2], q3 = wq[3];
            u64 s2 = 0ULL;
            s2 = fma2(q0.x, out2[0], s2);
            s2 = fma2(q0.y, out2[1], s2);
            s2 = fma2(q1.x, out2[2], s2);
            s2 = fma2(q1.y, out2[3], s2);
            s2 = fma2(q2.x, out2[4], s2);
            s2 = fma2(q2.y, out2[5], s2);
            s2 = fma2(q3.x, out2[6], s2);
            s2 = fma2(q3.y, out2[7], s2);
            float lo, hi;
            unpack2(s2, lo, hi);
            xe_out[(cbase + j) * Bb + b] = xb + sm.sb3[j] + (lo + hi);
        }
    }
}

// ---------------- final: compact sums, then coalesced output -----------------
__global__ void __launch_bounds__(128) k_sum(const float* __restrict__ xe) {
    int n = 1800 + blockIdx.x;      // 200 blocks
    int b = threadIdx.x;
    float s = 0.f;
    int rs = g_rsD[n], re = g_rsD[n + 1];
    for (int p = rs; p < re; p++) s += xe[g_rowidx[p] + b];
    g_osum[blockIdx.x * Bb + b] = s;
}

__global__ void __launch_bounds__(256) k_out(float* __restrict__ out) {
    int t = blockIdx.x * 256 + threadIdx.x;   // 1000 blocks cover 128*2000
    if (t < Bb * Nn) {
        int n = t % Nn;                        // out index (b-major)
        int b = t / Nn;
        out[t] = (n >= 1800) ? g_osum[(n - 1800) * Bb + b] : 0.0f;
    }
    if (t < Nn) { g_cntD[t] = 0; g_cntS[t] = 0; }   // ready for next call
}

// ---------------- launch ----------------------------------------------------
extern "C" void kernel_launch(void* const* d_in, const int* in_sizes, int n_in,
                              void* d_out, int out_size) {
    const float* x   = (const float*)d_in[0];
    const float* w1  = (const float*)d_in[1];
    const float* b1  = (const float*)d_in[2];
    const float* w2  = (const float*)d_in[3];
    const float* b2  = (const float*)d_in[4];
    const float* w3  = (const float*)d_in[5];
    const float* b3  = (const float*)d_in[6];
    const float* g1  = (const float*)d_in[7];
    const float* be1 = (const float*)d_in[8];
    const float* g2  = (const float*)d_in[9];
    const float* be2 = (const float*)d_in[10];
    const int*   ei  = (const int*)d_in[11];
    float* out = (float*)d_out;

    const int* src = ei;
    const int* dst = ei + Ee;

    dim3 gInit(63, 4);
    k_init<<<gInit, 256>>>(x, src, dst);
    k_scan<<<2, 1024>>>();
    k_build<<<(Ee + 255) / 256, 256>>>(w1, w3, b3, src, dst);

    static float* xeA = nullptr;
    static float* xeB = nullptr;
    static float* xT  = nullptr;
    if (!xeA) {
        cudaGetSymbolAddress((void**)&xeA, g_xeA);
        cudaGetSymbolAddress((void**)&xeB, g_xeB);
        cudaGetSymbolAddress((void**)&xT,  g_xT);
    }

    k_layer<<<2000, 128>>>(xT,  1, xeA, b1, w2, b2, g1, be1, g2, be2);
    k_layer<<<1600, 128>>>(xeA, 0, xeB, b1, w2, b2, g1, be1, g2, be2);
    k_layer<<<1600, 128>>>(xeB, 0, xeA, b1, w2, b2, g1, be1, g2, be2);
    k_layer<<<1600, 128>>>(xeA, 0, xeB, b1, w2, b2, g1, be1, g2, be2);

    k_sum<<<200, 128>>>(xeB);
    k_out<<<(Bb * Nn + 255) / 256, 256>>>(out);
}

// round 11
// speedup vs baseline: 1.0173x; 1.0173x over previous
#include <cuda_runtime.h>
#include <math.h>

#define Nn 2000
#define Ee 20000
#define Cc 16
#define Bb 128
#define EPS 1e-5f
#define CHUNK 128

typedef unsigned long long u64;

__device__ __forceinline__ bool is_func(int n) { return n >= 200 && n < 1800; }

// ---- packed f32x2 helpers ---------------------------------------------------
__device__ __forceinline__ u64 fma2(u64 a, u64 b, u64 c) {
    u64 d;
    asm("fma.rn.f32x2 %0, %1, %2, %3;" : "=l"(d) : "l"(a), "l"(b), "l"(c));
    return d;
}
__device__ __forceinline__ u64 splat2(float x) {
    u64 d;
    unsigned r = __float_as_uint(x);
    asm("mov.b64 %0, {%1, %1};" : "=l"(d) : "r"(r));
    return d;
}
__device__ __forceinline__ void unpack2(u64 v, float& lo, float& hi) {
    unsigned a, b;
    asm("mov.b64 {%0, %1}, %2;" : "=r"(a), "=r"(b) : "l"(v));
    lo = __uint_as_float(a); hi = __uint_as_float(b);
}
__device__ __forceinline__ u64 pack2(float lo, float hi) {
    u64 d;
    unsigned a = __float_as_uint(lo), b = __float_as_uint(hi);
    asm("mov.b64 %0, {%1, %2};" : "=l"(d) : "r"(a), "r"(b));
    return d;
}

// ---------------- device scratch (allocation-free) --------------------------
__device__ float g_xT[Nn * Bb];
__device__ float g_xeA[Ee * Bb];
__device__ float g_xeB[Ee * Bb];
__device__ float g_pw1[Ee * Cc];
__device__ float g_pw3m[Ee * Cc];
__device__ float g_pb3[Ee];
__device__ int   g_psrcd[Ee];
__device__ int   g_rowidx[Ee];
__device__ float g_osum[200 * Bb];
__device__ int   g_cntD[Nn], g_cntS[Nn];       // zero at load; re-zeroed by k_out
__device__ int   g_cntO[Nn], g_cntM[Nn];       // src-class histograms (O: dst>=1800, M: func dst)
__device__ int   g_rsD[Nn + 1], g_rsS[Nn + 1];
__device__ int   g_curD[Nn];
__device__ int   g_cur0[Nn], g_cur1[Nn], g_cur2[Nn];  // class cursors within src rows
__device__ int   g_sb1[Nn];    // rsS + O          (scatter end for last layer)
__device__ int   g_sb2[Nn];    // rsS + O + M      (scatter end for layers 0-2, k_const)

// ---------------- preprocessing ---------------------------------------------
__global__ void __launch_bounds__(256) k_init(
        const float* __restrict__ x,
        const int* __restrict__ src, const int* __restrict__ dst) {
    __shared__ float tile[32][33];
    int bx = blockIdx.x, by = blockIdx.y;
    int tx = threadIdx.x & 31, ty = threadIdx.x >> 5;
    int n0 = bx * 32, b0 = by * 32;
#pragma unroll
    for (int k = 0; k < 32; k += 8) {
        int n = n0 + tx, b = b0 + ty + k;
        if (n < Nn) tile[ty + k][tx] = x[b * Nn + n];
    }
    __syncthreads();
#pragma unroll
    for (int k = 0; k < 32; k += 8) {
        int n = n0 + ty + k, b = b0 + tx;
        if (n < Nn) g_xT[n * Bb + b] = tile[tx][ty + k];
    }
    int t = (blockIdx.y * gridDim.x + blockIdx.x) * 256 + threadIdx.x;
    if (t < Ee) {
        int d = dst[t], s = src[t];
        atomicAdd(&g_cntD[d], 1);
        atomicAdd(&g_cntS[s], 1);
        if (d >= 1800)      atomicAdd(&g_cntO[s], 1);
        else if (d >= 200)  atomicAdd(&g_cntM[s], 1);
    }
}

__global__ void __launch_bounds__(1024) k_scan() {
    __shared__ int sh[2048];
    const int* cnt = blockIdx.x ? g_cntS : g_cntD;
    int* rs = blockIdx.x ? g_rsS : g_rsD;
    int t = threadIdx.x;
    sh[t]        = (t < Nn) ? cnt[t] : 0;
    sh[t + 1024] = (t + 1024 < Nn) ? cnt[t + 1024] : 0;
    __syncthreads();
    for (int off = 1; off < 2048; off <<= 1) {
        int v0 = (t >= off) ? sh[t - off] : 0;
        int v1 = (t + 1024 >= off) ? sh[t + 1024 - off] : 0;
        __syncthreads();
        sh[t] += v0;
        sh[t + 1024] += v1;
        __syncthreads();
    }
#pragma unroll
    for (int h = 0; h < 2; h++) {
        int i = t + h * 1024;
        if (i < Nn) {
            int v = (i == 0) ? 0 : sh[i - 1];
            rs[i] = v;
            if (blockIdx.x == 0) {          // dst side
                g_curD[i] = v;
            } else {                        // src side: class cursors + bounds
                int o = g_cntO[i], m = g_cntM[i];
                g_cur0[i] = v;
                g_cur1[i] = v + o;
                g_cur2[i] = v + o + m;
                g_sb1[i]  = v + o;
                g_sb2[i]  = v + o + m;
            }
        }
    }
    if (t == 0) rs[Nn] = sh[Nn - 1];
}

__global__ void __launch_bounds__(256) k_build(
        const float* __restrict__ w1, const float* __restrict__ w3,
        const float* __restrict__ b3,
        const int* __restrict__ src, const int* __restrict__ dst) {
    __shared__ int sE[256], sPd[256], sPs[256];
    __shared__ float sFm[256];
    int e = blockIdx.x * 256 + threadIdx.x;
    int nEdge = min(256, Ee - blockIdx.x * 256);
    if (e < Ee) {
        int s = src[e], d = dst[e];
        int pd = atomicAdd(&g_curD[d], 1);
        int* cur = (d >= 1800) ? g_cur0 : ((d >= 200) ? g_cur1 : g_cur2);
        int ps = atomicAdd(&cur[s], 1);
        g_psrcd[pd]  = s * Bb;
        g_rowidx[pd] = ps * Bb;
        g_pb3[ps]    = b3[e];
        sE[threadIdx.x]  = e;
        sPd[threadIdx.x] = pd;
        sPs[threadIdx.x] = ps;
        sFm[threadIdx.x] = is_func(s) ? 1.0f : 0.0f;
    }
    __syncthreads();
    for (int i = threadIdx.x; i < nEdge * 16; i += 256) {
        int j = i >> 4, c = i & 15;
        int e2 = sE[j];
        g_pw1[sPd[j] * 16 + c]  = w1[e2 * 16 + c];
        g_pw3m[sPs[j] * 16 + c] = w3[e2 * 16 + c] * sFm[j];
    }
}

// ---------------- shared layout ----------------------------------------------
struct SmemT {
    union {
        float4 stage4[CHUNK * 4];
        float  stage[CHUNK * 16];
        float  shh[128][17];
    };
    float4 shw4[16][4];
    float  shs[8][16], shs2[8][16];
    float  shscale[16], shshift[16];
    int    sidx[CHUNK];
    float  sb3[CHUNK];
};

// ---------------- BN + ELU ---------------------------------------------------
__device__ __forceinline__ void bn_elu(float* acc, int n, int b,
                                       const float* __restrict__ gamma,
                                       const float* __restrict__ beta,
                                       SmemT* sm) {
    __syncthreads();
#pragma unroll
    for (int c = 0; c < 16; c++) sm->shh[b][c] = acc[c];
    __syncthreads();
    int c0 = b & 15, gg = b >> 4;
    float s = 0.f, s2 = 0.f;
#pragma unroll
    for (int k = 0; k < 16; k++) {
        float v = sm->shh[gg + 8 * k][c0];
        s += v; s2 += v * v;
    }
    sm->shs[gg][c0] = s;
    sm->shs2[gg][c0] = s2;
    __syncthreads();
    if (b < 16) {
        float S = 0.f, S2 = 0.f;
#pragma unroll
        for (int g = 0; g < 8; g++) { S += sm->shs[g][b]; S2 += sm->shs2[g][b]; }
        float m   = S * (1.0f / 128.0f);
        float var = S2 * (1.0f / 128.0f) - m * m;
        float rsg = rsqrtf(var + EPS);
        float sc  = gamma[n * 16 + b] * rsg;
        sm->shscale[b] = sc;
        sm->shshift[b] = beta[n * 16 + b] - m * sc;
    }
    __syncthreads();
#pragma unroll
    for (int c = 0; c < 16; c++) {
        float v = acc[c] * sm->shscale[c] + sm->shshift[c];
        acc[c] = v > 0.f ? v : (__expf(v) - 1.0f);
    }
}

// ---------------- fused per-layer kernel -------------------------------------
// qend: g_sb2 for layers 0-2 (skip dst<200 edges), g_sb1 for last layer
// (only dst>=1800 edges survive to k_sum).
__global__ void __launch_bounds__(128, 12) k_layer(
    const float* __restrict__ xe_rows, int use_psrc,
    float* __restrict__ xe_out, const int* __restrict__ qend,
    const float* __restrict__ b1, const float* __restrict__ w2,
    const float* __restrict__ b2,
    const float* __restrict__ g1, const float* __restrict__ be1,
    const float* __restrict__ g2, const float* __restrict__ be2) {
    __shared__ SmemT sm;
    int t = blockIdx.x;
    int b = threadIdx.x;

    if (t >= 1600) {   // const-edge writer (layer-0 grid only)
        int i = t - 1600;
        int n = (i < 200) ? i : (1600 + i);
        float xb = g_xT[n * Bb + b];
        int qs = g_rsS[n], qe = g_sb2[n];   // skip dead dst<200 rows
        for (int q = qs; q < qe; q++) {
            float v = xb + g_pb3[q];
            g_xeA[q * Bb + b] = v;
            g_xeB[q * Bb + b] = v;
        }
        return;
    }

    int n = 200 + t;
    const int* rowix = use_psrc ? g_psrcd : g_rowidx;

    u64 acc2[8];
    {
        const ulonglong2* bp = (const ulonglong2*)(b1 + n * 16);
#pragma unroll
        for (int k = 0; k < 4; k++) {
            ulonglong2 q = bp[k];
            acc2[2 * k] = q.x; acc2[2 * k + 1] = q.y;
        }
    }

    // ---- gather ----
    int rs = g_rsD[n], re = g_rsD[n + 1];
    for (int cbase = rs; cbase < re; cbase += CHUNK) {
        int cnt = min(CHUNK, re - cbase);
        __syncthreads();
        for (int i = b; i < cnt * 16; i += 128) sm.stage[i] = g_pw1[cbase * 16 + i];
        if (b < cnt) sm.sidx[b] = rowix[cbase + b];
        __syncthreads();
        for (int jb = 0; jb < cnt; jb += 8) {
            float xv[8];
#pragma unroll
            for (int j = 0; j < 8; j++) {
                int jj = jb + j;
                xv[j] = (jj < cnt) ? xe_rows[sm.sidx[jj] + b] : 0.0f;
            }
#pragma unroll
            for (int j = 0; j < 8; j++) {
                int jj = jb + j;
                if (jj < cnt) {
                    u64 xv2 = splat2(xv[j]);
                    const ulonglong2* wp = (const ulonglong2*)&sm.stage[jj * 16];
                    ulonglong2 q0 = wp[0], q1 = wp[1], q2 = wp[2], q3 = wp[3];
                    acc2[0] = fma2(q0.x, xv2, acc2[0]);
                    acc2[1] = fma2(q0.y, xv2, acc2[1]);
                    acc2[2] = fma2(q1.x, xv2, acc2[2]);
                    acc2[3] = fma2(q1.y, xv2, acc2[3]);
                    acc2[4] = fma2(q2.x, xv2, acc2[4]);
                    acc2[5] = fma2(q2.y, xv2, acc2[5]);
                    acc2[6] = fma2(q3.x, xv2, acc2[6]);
                    acc2[7] = fma2(q3.y, xv2, acc2[7]);
                }
            }
        }
    }

    float acc[16];
#pragma unroll
    for (int k = 0; k < 8; k++) unpack2(acc2[k], acc[2 * k], acc[2 * k + 1]);

    bn_elu(acc, n, b, g1, be1, &sm);

    // ---- 16x16 matmul ----
    __syncthreads();
#pragma unroll
    for (int c = 0; c < 16; c++) sm.shh[b][c] = acc[c];
    {
        const float4* w2p = (const float4*)(w2 + n * 256);
        for (int i = b; i < 64; i += 128) sm.shw4[i >> 2][i & 3] = w2p[i];
    }
    __syncthreads();

    u64 out2[8];
    {
        const ulonglong2* bp = (const ulonglong2*)(b2 + n * 16);
#pragma unroll
        for (int k = 0; k < 4; k++) {
            ulonglong2 q = bp[k];
            out2[2 * k] = q.x; out2[2 * k + 1] = q.y;
        }
    }
#pragma unroll
    for (int c = 0; c < 16; c++) {
        u64 v2 = splat2(sm.shh[b][c]);
        const ulonglong2* wp = (const ulonglong2*)&sm.shw4[c][0];
        ulonglong2 q0 = wp[0], q1 = wp[1], q2 = wp[2], q3 = wp[3];
        out2[0] = fma2(q0.x, v2, out2[0]);
        out2[1] = fma2(q0.y, v2, out2[1]);
        out2[2] = fma2(q1.x, v2, out2[2]);
        out2[3] = fma2(q1.y, v2, out2[3]);
        out2[4] = fma2(q2.x, v2, out2[4]);
        out2[5] = fma2(q2.y, v2, out2[5]);
        out2[6] = fma2(q3.x, v2, out2[6]);
        out2[7] = fma2(q3.y, v2, out2[7]);
    }

    float out[16];
#pragma unroll
    for (int k = 0; k < 8; k++) unpack2(out2[k], out[2 * k], out[2 * k + 1]);

    bn_elu(out, n, b, g2, be2, &sm);

#pragma unroll
    for (int k = 0; k < 8; k++) out2[k] = pack2(out[2 * k], out[2 * k + 1]);

    // ---- scatter (live edges only) ----
    float xb = g_xT[n * Bb + b];
    int qs = g_rsS[n], qe = qend[n];
    for (int cbase = qs; cbase < qe; cbase += CHUNK) {
        int cnt = min(CHUNK, qe - cbase);
        __syncthreads();
        for (int i = b; i < cnt * 16; i += 128) sm.stage[i] = g_pw3m[cbase * 16 + i];
        if (b < cnt) sm.sb3[b] = g_pb3[cbase + b];
        __syncthreads();
        for (int j = 0; j < cnt; j++) {
            const ulonglong2* wq = (const ulonglong2*)&sm.stage[j * 16];
            ulonglong2 q0 = wq[0], q1 = wq[1], q2 = wq[2], q3 = wq[3];
            u64 s2 = 0ULL;
            s2 = fma2(q0.x, out2[0], s2);
            s2 = fma2(q0.y, out2[1], s2);
            s2 = fma2(q1.x, out2[2], s2);
            s2 = fma2(q1.y, out2[3], s2);
            s2 = fma2(q2.x, out2[4], s2);
            s2 = fma2(q2.y, out2[5], s2);
            s2 = fma2(q3.x, out2[6], s2);
            s2 = fma2(q3.y, out2[7], s2);
            float lo, hi;
            unpack2(s2, lo, hi);
            xe_out[(cbase + j) * Bb + b] = xb + sm.sb3[j] + (lo + hi);
        }
    }
}

// ---------------- final: compact sums, then coalesced output -----------------
__global__ void __launch_bounds__(128) k_sum(const float* __restrict__ xe) {
    int n = 1800 + blockIdx.x;
    int b = threadIdx.x;
    float s = 0.f;
    int rs = g_rsD[n], re = g_rsD[n + 1];
    for (int p = rs; p < re; p++) s += xe[g_rowidx[p] + b];
    g_osum[blockIdx.x * Bb + b] = s;
}

__global__ void __launch_bounds__(256) k_out(float* __restrict__ out) {
    int t = blockIdx.x * 256 + threadIdx.x;
    if (t < Bb * Nn) {
        int n = t % Nn;
        int b = t / Nn;
        out[t] = (n >= 1800) ? g_osum[(n - 1800) * Bb + b] : 0.0f;
    }
    if (t < Nn) { g_cntD[t] = 0; g_cntS[t] = 0; g_cntO[t] = 0; g_cntM[t] = 0; }
}

// ---------------- launch ----------------------------------------------------
extern "C" void kernel_launch(void* const* d_in, const int* in_sizes, int n_in,
                              void* d_out, int out_size) {
    const float* x   = (const float*)d_in[0];
    const float* w1  = (const float*)d_in[1];
    const float* b1  = (const float*)d_in[2];
    const float* w2  = (const float*)d_in[3];
    const float* b2  = (const float*)d_in[4];
    const float* w3  = (const float*)d_in[5];
    const float* b3  = (const float*)d_in[6];
    const float* g1  = (const float*)d_in[7];
    const float* be1 = (const float*)d_in[8];
    const float* g2  = (const float*)d_in[9];
    const float* be2 = (const float*)d_in[10];
    const int*   ei  = (const int*)d_in[11];
    float* out = (float*)d_out;

    const int* src = ei;
    const int* dst = ei + Ee;

    static float* xeA = nullptr;
    static float* xeB = nullptr;
    static float* xT  = nullptr;
    static int*   sb1 = nullptr;
    static int*   sb2 = nullptr;
    if (!xeA) {
        cudaGetSymbolAddress((void**)&xeA, g_xeA);
        cudaGetSymbolAddress((void**)&xeB, g_xeB);
        cudaGetSymbolAddress((void**)&xT,  g_xT);
        cudaGetSymbolAddress((void**)&sb1, g_sb1);
        cudaGetSymbolAddress((void**)&sb2, g_sb2);
        // unlock smem carveout so 12 blocks x 12KB fit per SM
        cudaFuncSetAttribute(k_layer,
            cudaFuncAttributePreferredSharedMemoryCarveout, 100);
    }

    dim3 gInit(63, 4);
    k_init<<<gInit, 256>>>(x, src, dst);
    k_scan<<<2, 1024>>>();
    k_build<<<(Ee + 255) / 256, 256>>>(w1, w3, b3, src, dst);

    k_layer<<<2000, 128>>>(xT,  1, xeA, sb2, b1, w2, b2, g1, be1, g2, be2);
    k_layer<<<1600, 128>>>(xeA, 0, xeB, sb2, b1, w2, b2, g1, be1, g2, be2);
    k_layer<<<1600, 128>>>(xeB, 0, xeA, sb2, b1, w2, b2, g1, be1, g2, be2);
    k_layer<<<1600, 128>>>(xeA, 0, xeB, sb1, b1, w2, b2, g1, be1, g2, be2);

    k_sum<<<200, 128>>>(xeB);
    k_out<<<(Bb * Nn + 255) / 256, 256>>>(out);
}